// round 2
// baseline (speedup 1.0000x reference)
#include <cuda_runtime.h>
#include <math.h>

#define BB 8
#define CC 64
#define HH 256
#define WW 256
#define EE 8192
#define HWSZ 65536
typedef unsigned long long u64;

__device__ float g_q[8*8*64*EE];
__device__ float g_k[8*8*64*EE];
__device__ float g_v[8*8*64*EE];
__device__ float g_Sp[16*64*4096];
__device__ float g_P[64*4096];
__device__ float g_y[BB*CC*HWSZ];
__device__ float g_x1[BB*CC*HWSZ];
__device__ float g_t[BB*CC*HWSZ];
__device__ float g_wqkvT[64*192];
__device__ float g_bqkv[192];
__device__ float g_woT[36864];
__device__ float g_wf1T[36864];
__device__ float g_wf2T[36864];

__device__ __forceinline__ u64 pack2(float lo, float hi){
    u64 r; asm("mov.b64 %0, {%1, %2};" : "=l"(r) : "f"(lo), "f"(hi)); return r; }
__device__ __forceinline__ u64 dup2(float v){ return pack2(v, v); }
__device__ __forceinline__ void fma2(u64 &a, u64 b, u64 c){
    asm("fma.rn.f32x2 %0, %1, %2, %0;" : "+l"(a) : "l"(b), "l"(c)); }
__device__ __forceinline__ float2 unpack2(u64 v){
    float2 f; asm("mov.b64 {%0, %1}, %2;" : "=f"(f.x), "=f"(f.y) : "l"(v)); return f; }
__device__ __forceinline__ int refl(int i, int n){
    if (i < 0) i = -i; if (i >= n) i = 2*n-2-i; return i; }
__device__ __forceinline__ float lrelu(float v){ return v > 0.f ? v : 0.2f*v; }

__global__ void xform_kernel(const float* __restrict__ wq, const float* __restrict__ bq,
                             const float* __restrict__ wk, const float* __restrict__ bk,
                             const float* __restrict__ wv, const float* __restrict__ bv,
                             const float* __restrict__ wo, const float* __restrict__ wf1,
                             const float* __restrict__ wf2){
    int idx = blockIdx.x*256 + threadIdx.x;
    if (idx < 12288){
        int ci = idx/192, oc = idx - ci*192; float v;
        if (oc < 64) v = wq[oc*64+ci]; else if (oc < 128) v = wk[(oc-64)*64+ci];
        else v = wv[(oc-128)*64+ci];
        g_wqkvT[idx] = v;
    }
    if (idx < 192)
        g_bqkv[idx] = (idx<64) ? bq[idx] : (idx<128 ? bk[idx-64] : bv[idx-128]);
    if (idx < 36864){
        int ci = idx/576, rem = idx - ci*576, t = rem>>6, o = rem&63;
        int s = (o*64+ci)*9 + t;
        g_woT[idx] = wo[s]; g_wf1T[idx] = wf1[s]; g_wf2T[idx] = wf2[s];
    }
}

// 1x1 conv -> q,k,v in windowed layout [bh][win][e], e = d*1024+py*32+px
__global__ __launch_bounds__(256) void qkv_kernel(const float* __restrict__ x){
    extern __shared__ float sm[];
    float* sW = sm; float* sB = sm+12288; float* sX = sm+12480;
    const int b = blockIdx.z, y = blockIdx.y, x0 = blockIdx.x*64;
    const int tid = threadIdx.x;
    for (int i = tid; i < 12288; i += 256) sW[i] = g_wqkvT[i];
    if (tid < 192) sB[tid] = g_bqkv[tid];
    for (int i = tid; i < 4096; i += 256){
        int ci = i>>6, p = i&63;
        sX[i] = x[(b*CC+ci)*HWSZ + y*256 + x0 + p];
    }
    __syncthreads();
    const int og = tid>>5, oc0 = og*24, ps = tid&31;
    u64 acc[12][2];
    #pragma unroll
    for (int op = 0; op < 12; op++){
        u64 bp = pack2(sB[oc0+2*op], sB[oc0+2*op+1]);
        acc[op][0] = bp; acc[op][1] = bp;
    }
    for (int ci = 0; ci < 64; ci++){
        float2 xv = *(const float2*)&sX[(ci<<6)+(ps<<1)];
        u64 xa = dup2(xv.x), xb = dup2(xv.y);
        const u64* wp = (const u64*)&sW[ci*192 + oc0];
        #pragma unroll
        for (int op = 0; op < 12; op++){
            u64 wv = wp[op];
            fma2(acc[op][0], wv, xa); fma2(acc[op][1], wv, xb);
        }
    }
    const int pxg = x0 + (ps<<1);
    const int win = ((y>>5)<<3) + (pxg>>5);
    const int py = y&31, pxx = pxg&31;
    #pragma unroll
    for (int op = 0; op < 12; op++){
        float2 p0 = unpack2(acc[op][0]), p1 = unpack2(acc[op][1]);
        #pragma unroll
        for (int hf = 0; hf < 2; hf++){
            int oc = oc0 + 2*op + hf;
            float2 v = hf ? make_float2(p0.y,p1.y) : make_float2(p0.x,p1.x);
            int t3 = oc>>6, c = oc&63, h = c>>3, d = c&7;
            float* base = (t3==0) ? g_q : (t3==1 ? g_k : g_v);
            *(float2*)&base[((b*8+h)*64+win)*EE + d*1024 + py*32 + pxx] = v;
        }
    }
}

// partial scores over 512-wide e-slice: grid 1024 = 64bh x 16 slices
__global__ __launch_bounds__(256) void attn_scores_kernel(){
    __shared__ float Qs[64*65];
    __shared__ float Ks[64*65];
    const int bh = blockIdx.x>>4, sl = blockIdx.x&15, e0 = sl*512;
    const int tid = threadIdx.x;
    const int qi0 = (tid>>4)<<2, ki0 = (tid&15)<<2;
    const float* Qg = g_q + bh*(64*EE);
    const float* Kg = g_k + bh*(64*EE);
    float acc[4][4] = {};
    for (int ec = 0; ec < 8; ec++){
        __syncthreads();
        for (int i = tid; i < 4096; i += 256){
            int qi = i>>6, e = i&63;
            Qs[e*65+qi] = Qg[qi*EE + e0 + ec*64 + e];
            Ks[e*65+qi] = Kg[qi*EE + e0 + ec*64 + e];
        }
        __syncthreads();
        #pragma unroll 4
        for (int e = 0; e < 64; e++){
            float q0=Qs[e*65+qi0],q1=Qs[e*65+qi0+1],q2=Qs[e*65+qi0+2],q3=Qs[e*65+qi0+3];
            float k0=Ks[e*65+ki0],k1=Ks[e*65+ki0+1],k2=Ks[e*65+ki0+2],k3=Ks[e*65+ki0+3];
            acc[0][0]+=q0*k0; acc[0][1]+=q0*k1; acc[0][2]+=q0*k2; acc[0][3]+=q0*k3;
            acc[1][0]+=q1*k0; acc[1][1]+=q1*k1; acc[1][2]+=q1*k2; acc[1][3]+=q1*k3;
            acc[2][0]+=q2*k0; acc[2][1]+=q2*k1; acc[2][2]+=q2*k2; acc[2][3]+=q2*k3;
            acc[3][0]+=q3*k0; acc[3][1]+=q3*k1; acc[3][2]+=q3*k2; acc[3][3]+=q3*k3;
        }
    }
    float* Sp = g_Sp + (sl*64+bh)*4096;
    #pragma unroll
    for (int i = 0; i < 4; i++)
        #pragma unroll
        for (int j = 0; j < 4; j++)
            Sp[(qi0+i)*64 + ki0+j] = acc[i][j];
}

__global__ void softmax_kernel(){
    const int bh = blockIdx.x, qi = threadIdx.x;
    const float scale = 0.011048543456039806f; // 1/sqrt(8192)
    float row[64];
    for (int k = 0; k < 64; k++){
        float s = 0.f;
        for (int sl = 0; sl < 16; sl++) s += g_Sp[(sl*64+bh)*4096 + qi*64 + k];
        row[k] = s*scale;
    }
    float m = row[0];
    for (int k = 1; k < 64; k++) m = fmaxf(m, row[k]);
    float sum = 0.f;
    for (int k = 0; k < 64; k++){ row[k] = __expf(row[k]-m); sum += row[k]; }
    float inv = 1.f/sum;
    for (int k = 0; k < 64; k++) g_P[bh*4096 + qi*64 + k] = row[k]*inv;
}

// Y = P @ V, writing un-windowed NCHW. grid 2048 = 64bh x 32 e-chunks
__global__ __launch_bounds__(256) void attn_pv_kernel(){
    __shared__ float Ps[4096];
    __shared__ float Vs[16*256];
    const int bh = blockIdx.x>>5, ec = blockIdx.x&31, e0 = ec*256;
    const int tid = threadIdx.x;
    for (int i = tid; i < 4096; i += 256) Ps[i] = g_P[bh*4096 + i];
    const int q0 = (tid>>5)*8, es = tid&31;
    const float* Vg = g_v + bh*(64*EE);
    float acc[8][8] = {};
    for (int kc = 0; kc < 4; kc++){
        __syncthreads();
        for (int i = tid; i < 4096; i += 256){
            int k = i>>8, e = i&255;
            Vs[i] = Vg[(kc*16+k)*EE + e0 + e];
        }
        __syncthreads();
        #pragma unroll
        for (int k = 0; k < 16; k++){
            float4 v0 = *(const float4*)&Vs[k*256 + es*8];
            float4 v1 = *(const float4*)&Vs[k*256 + es*8 + 4];
            #pragma unroll
            for (int i = 0; i < 8; i++){
                float p = Ps[(q0+i)*64 + kc*16 + k];
                acc[i][0]+=p*v0.x; acc[i][1]+=p*v0.y; acc[i][2]+=p*v0.z; acc[i][3]+=p*v0.w;
                acc[i][4]+=p*v1.x; acc[i][5]+=p*v1.y; acc[i][6]+=p*v1.z; acc[i][7]+=p*v1.w;
            }
        }
    }
    const int b = bh>>3, h = bh&7;
    const int eg = e0 + es*8;
    const int d = eg>>10, py = (eg>>5)&31, px = eg&31;
    #pragma unroll
    for (int i = 0; i < 8; i++){
        int q = q0+i, oy = q>>3, ox = q&7;
        float* dst = g_y + (b*CC + h*8 + d)*HWSZ + (oy*32+py)*256 + ox*32 + px;
        *(float4*)dst     = make_float4(acc[i][0],acc[i][1],acc[i][2],acc[i][3]);
        *(float4*)(dst+4) = make_float4(acc[i][4],acc[i][5],acc[i][6],acc[i][7]);
    }
}

// 3x3 reflect conv, dilation D, lrelu, optional residual add after lrelu
template<int D>
__global__ __launch_bounds__(256, 2) void conv3x3_kernel(
        const float* __restrict__ src, const float* __restrict__ wT,
        const float* __restrict__ bias, const float* __restrict__ resid,
        float* __restrict__ dst){
    const int ROWS = 8 + 2*D, COLS = 32 + 2*D;
    extern __shared__ float sm[];
    float* sIn = sm;             // [16][12][40]
    float* sW  = sm + 16*12*40;  // [16][9][64]
    const int b = blockIdx.z, y0 = blockIdx.y*8, x0 = blockIdx.x*32;
    const int tid = threadIdx.x;
    const int o0 = (tid>>6)<<4;
    const int slot = tid&63, sy = slot>>3, sx = (slot&7)<<2;
    u64 acc[8][4];
    #pragma unroll
    for (int op = 0; op < 8; op++){
        u64 bp = pack2(bias[o0+2*op], bias[o0+2*op+1]);
        acc[op][0]=bp; acc[op][1]=bp; acc[op][2]=bp; acc[op][3]=bp;
    }
    const int srcB = b*CC*HWSZ;
    for (int cc = 0; cc < 4; cc++){
        __syncthreads();
        for (int i = tid; i < 16*ROWS*COLS; i += 256){
            int ci = i/(ROWS*COLS), rem = i - ci*(ROWS*COLS);
            int r = rem/COLS, c2 = rem - r*COLS;
            int yg = refl(y0 - D + r, HH), xg = refl(x0 - D + c2, WW);
            sIn[(ci*12+r)*40 + c2] = src[srcB + (cc*16+ci)*HWSZ + yg*256 + xg];
        }
        const float* wc = wT + cc*9216;
        for (int i = tid; i < 9216; i += 256) sW[i] = wc[i];
        __syncthreads();
        for (int ci = 0; ci < 16; ci++){
            const float* inC = sIn + ci*480;
            const float* wC  = sW + ci*576;
            #pragma unroll
            for (int ky = 0; ky < 3; ky++){
                const float* rp = inC + (sy + ky*D)*40 + sx;
                float4 a0 = *(const float4*)rp;
                float4 a1 = *(const float4*)(rp+4);
                u64 xd[8];
                xd[0]=dup2(a0.x); xd[1]=dup2(a0.y); xd[2]=dup2(a0.z); xd[3]=dup2(a0.w);
                xd[4]=dup2(a1.x); xd[5]=dup2(a1.y);
                if (D == 2){ xd[6]=dup2(a1.z); xd[7]=dup2(a1.w); }
                #pragma unroll
                for (int kx = 0; kx < 3; kx++){
                    const u64* wp = (const u64*)(wC + (ky*3+kx)*64 + o0);
                    #pragma unroll
                    for (int op = 0; op < 8; op++){
                        u64 wv = wp[op];
                        fma2(acc[op][0], wv, xd[kx*D+0]);
                        fma2(acc[op][1], wv, xd[kx*D+1]);
                        fma2(acc[op][2], wv, xd[kx*D+2]);
                        fma2(acc[op][3], wv, xd[kx*D+3]);
                    }
                }
            }
        }
    }
    const int pixB = b*CC*HWSZ + (y0+sy)*256 + x0 + sx;
    #pragma unroll
    for (int op = 0; op < 8; op++){
        float2 j0=unpack2(acc[op][0]), j1=unpack2(acc[op][1]);
        float2 j2=unpack2(acc[op][2]), j3=unpack2(acc[op][3]);
        float4 lo = make_float4(lrelu(j0.x),lrelu(j1.x),lrelu(j2.x),lrelu(j3.x));
        float4 hi = make_float4(lrelu(j0.y),lrelu(j1.y),lrelu(j2.y),lrelu(j3.y));
        int aLo = pixB + (o0+2*op)*HWSZ, aHi = aLo + HWSZ;
        if (resid){
            float4 r0 = *(const float4*)&resid[aLo];
            float4 r1 = *(const float4*)&resid[aHi];
            lo.x+=r0.x; lo.y+=r0.y; lo.z+=r0.z; lo.w+=r0.w;
            hi.x+=r1.x; hi.y+=r1.y; hi.z+=r1.z; hi.w+=r1.w;
        }
        *(float4*)&dst[aLo] = lo;
        *(float4*)&dst[aHi] = hi;
    }
}

extern "C" void kernel_launch(void* const* d_in, const int* in_sizes, int n_in,
                              void* d_out, int out_size){
    const float* x   = (const float*)d_in[0];
    const float* wq  = (const float*)d_in[2];
    const float* bq  = (const float*)d_in[3];
    const float* wk  = (const float*)d_in[4];
    const float* bk  = (const float*)d_in[5];
    const float* wv  = (const float*)d_in[6];
    const float* bv  = (const float*)d_in[7];
    const float* wo  = (const float*)d_in[8];
    const float* bo  = (const float*)d_in[9];
    const float* wf1 = (const float*)d_in[10];
    const float* bf1 = (const float*)d_in[11];
    const float* wf2 = (const float*)d_in[12];
    const float* bf2 = (const float*)d_in[13];
    float* out = (float*)d_out;

    float *py, *px1, *pt, *pwo, *pwf1, *pwf2;
    cudaGetSymbolAddress((void**)&py,  g_y);
    cudaGetSymbolAddress((void**)&px1, g_x1);
    cudaGetSymbolAddress((void**)&pt,  g_t);
    cudaGetSymbolAddress((void**)&pwo, g_woT);
    cudaGetSymbolAddress((void**)&pwf1, g_wf1T);
    cudaGetSymbolAddress((void**)&pwf2, g_wf2T);

    const int QKV_SMEM  = (12288 + 192 + 4096) * 4;
    const int CONV_SMEM = (16*12*40 + 9216) * 4;
    cudaFuncSetAttribute(qkv_kernel, cudaFuncAttributeMaxDynamicSharedMemorySize, QKV_SMEM);
    cudaFuncSetAttribute(conv3x3_kernel<1>, cudaFuncAttributeMaxDynamicSharedMemorySize, CONV_SMEM);
    cudaFuncSetAttribute(conv3x3_kernel<2>, cudaFuncAttributeMaxDynamicSharedMemorySize, CONV_SMEM);

    xform_kernel<<<144, 256>>>(wq, bq, wk, bk, wv, bv, wo, wf1, wf2);
    qkv_kernel<<<dim3(WW/64, HH, BB), 256, QKV_SMEM>>>(x);
    attn_scores_kernel<<<1024, 256>>>();
    softmax_kernel<<<64, 64>>>();
    attn_pv_kernel<<<2048, 256>>>();
    dim3 cg(WW/32, HH/8, BB);
    conv3x3_kernel<1><<<cg, 256, CONV_SMEM>>>(py,  pwo,  bo,  x,    px1);
    conv3x3_kernel<2><<<cg, 256, CONV_SMEM>>>(px1, pwf1, bf1, nullptr, pt);
    conv3x3_kernel<1><<<cg, 256, CONV_SMEM>>>(pt,  pwf2, bf2, px1,  out);
}

// round 4
// speedup vs baseline: 1.4051x; 1.4051x over previous
#include <cuda_runtime.h>
#include <math.h>
#include <stdint.h>

#define BB 8
#define CC 64
#define HH 256
#define WW 256
#define EE 8192
#define HWSZ 65536
typedef unsigned long long u64;

__device__ float g_q[8*8*64*EE];
__device__ float g_k[8*8*64*EE];
__device__ float g_v[8*8*64*EE];
__device__ float g_Sp[16*64*4096];
__device__ float g_P[64*4096];
__device__ float g_y[BB*CC*HWSZ];
__device__ float g_x1[BB*CC*HWSZ];
__device__ float g_t[BB*CC*HWSZ];
__device__ float g_wqkvT[64*192];
__device__ float g_bqkv[192];
__device__ float g_wt[3*36864];   // per conv: [tap][ci][oc], tf32-rounded

__device__ __forceinline__ u64 pack2(float lo, float hi){
    u64 r; asm("mov.b64 %0, {%1, %2};" : "=l"(r) : "f"(lo), "f"(hi)); return r; }
__device__ __forceinline__ u64 dup2(float v){ return pack2(v, v); }
__device__ __forceinline__ void fma2(u64 &a, u64 b, u64 c){
    asm("fma.rn.f32x2 %0, %1, %2, %0;" : "+l"(a) : "l"(b), "l"(c)); }
__device__ __forceinline__ float2 unpack2(u64 v){
    float2 f; asm("mov.b64 {%0, %1}, %2;" : "=f"(f.x), "=f"(f.y) : "l"(v)); return f; }
__device__ __forceinline__ int refl(int i, int n){
    if (i < 0) i = -i; if (i >= n) i = 2*n-2-i; return i; }
__device__ __forceinline__ float lrelu(float v){ return v > 0.f ? v : 0.2f*v; }
__device__ __forceinline__ uint32_t f2tf32(float f){
    uint32_t u; asm("cvt.rna.tf32.f32 %0, %1;" : "=r"(u) : "f"(f)); return u; }

__device__ __forceinline__ void mma8(float* c, uint32_t a0, uint32_t a1, uint32_t a2,
                                     uint32_t a3, uint32_t b0, uint32_t b1){
    asm("mma.sync.aligned.m16n8k8.row.col.f32.tf32.tf32.f32 "
        "{%0,%1,%2,%3},{%4,%5,%6,%7},{%8,%9},{%0,%1,%2,%3};"
        : "+f"(c[0]),"+f"(c[1]),"+f"(c[2]),"+f"(c[3])
        : "r"(a0),"r"(a1),"r"(a2),"r"(a3),"r"(b0),"r"(b1));
}

// ---------- weight transform ----------
__global__ void xform_kernel(const float* __restrict__ wq, const float* __restrict__ bq,
                             const float* __restrict__ wk, const float* __restrict__ bk,
                             const float* __restrict__ wv, const float* __restrict__ bv,
                             const float* __restrict__ wo, const float* __restrict__ wf1,
                             const float* __restrict__ wf2){
    int idx = blockIdx.x*256 + threadIdx.x;
    if (idx < 12288){
        int ci = idx/192, oc = idx - ci*192; float v;
        if (oc < 64) v = wq[oc*64+ci]; else if (oc < 128) v = wk[(oc-64)*64+ci];
        else v = wv[(oc-128)*64+ci];
        g_wqkvT[idx] = v;
    }
    if (idx < 192)
        g_bqkv[idx] = (idx<64) ? bq[idx] : (idx<128 ? bk[idx-64] : bv[idx-128]);
    if (idx < 36864){
        int tap = idx>>12, rem = idx&4095, ci = rem>>6, oc = rem&63;
        int s = (oc*64+ci)*9 + tap;
        g_wt[idx]           = __uint_as_float(f2tf32(wo[s]));
        g_wt[36864 + idx]   = __uint_as_float(f2tf32(wf1[s]));
        g_wt[2*36864 + idx] = __uint_as_float(f2tf32(wf2[s]));
    }
}

// ---------- qkv 1x1 conv -> windowed layout ----------
__global__ __launch_bounds__(256) void qkv_kernel(const float* __restrict__ x){
    extern __shared__ float sm[];
    float* sW = sm; float* sB = sm+12288; float* sX = sm+12480;
    const int b = blockIdx.z, y = blockIdx.y, x0 = blockIdx.x*64;
    const int tid = threadIdx.x;
    for (int i = tid; i < 12288; i += 256) sW[i] = g_wqkvT[i];
    if (tid < 192) sB[tid] = g_bqkv[tid];
    for (int i = tid; i < 4096; i += 256){
        int ci = i>>6, p = i&63;
        sX[i] = x[(b*CC+ci)*HWSZ + y*256 + x0 + p];
    }
    __syncthreads();
    const int og = tid>>5, oc0 = og*24, ps = tid&31;
    u64 acc[12][2];
    #pragma unroll
    for (int op = 0; op < 12; op++){
        u64 bp = pack2(sB[oc0+2*op], sB[oc0+2*op+1]);
        acc[op][0] = bp; acc[op][1] = bp;
    }
    for (int ci = 0; ci < 64; ci++){
        float2 xv = *(const float2*)&sX[(ci<<6)+(ps<<1)];
        u64 xa = dup2(xv.x), xb = dup2(xv.y);
        const u64* wp = (const u64*)&sW[ci*192 + oc0];
        #pragma unroll
        for (int op = 0; op < 12; op++){
            u64 wv = wp[op];
            fma2(acc[op][0], wv, xa); fma2(acc[op][1], wv, xb);
        }
    }
    const int pxg = x0 + (ps<<1);
    const int win = ((y>>5)<<3) + (pxg>>5);
    const int py = y&31, pxx = pxg&31;
    #pragma unroll
    for (int op = 0; op < 12; op++){
        float2 p0 = unpack2(acc[op][0]), p1 = unpack2(acc[op][1]);
        #pragma unroll
        for (int hf = 0; hf < 2; hf++){
            int oc = oc0 + 2*op + hf;
            float2 v = hf ? make_float2(p0.y,p1.y) : make_float2(p0.x,p1.x);
            int t3 = oc>>6, c = oc&63, h = c>>3, d = c&7;
            float* base = (t3==0) ? g_q : (t3==1 ? g_k : g_v);
            *(float2*)&base[((b*8+h)*64+win)*EE + d*1024 + py*32 + pxx] = v;
        }
    }
}

// ---------- partial scores ----------
__global__ __launch_bounds__(256) void attn_scores_kernel(){
    __shared__ float Qs[64*65];
    __shared__ float Ks[64*65];
    const int bh = blockIdx.x>>4, sl = blockIdx.x&15, e0 = sl*512;
    const int tid = threadIdx.x;
    const int qi0 = (tid>>4)<<2, ki0 = (tid&15)<<2;
    const float* Qg = g_q + bh*(64*EE);
    const float* Kg = g_k + bh*(64*EE);
    float acc[4][4] = {};
    for (int ec = 0; ec < 8; ec++){
        __syncthreads();
        for (int i = tid; i < 4096; i += 256){
            int qi = i>>6, e = i&63;
            Qs[e*65+qi] = Qg[qi*EE + e0 + ec*64 + e];
            Ks[e*65+qi] = Kg[qi*EE + e0 + ec*64 + e];
        }
        __syncthreads();
        #pragma unroll 4
        for (int e = 0; e < 64; e++){
            float q0=Qs[e*65+qi0],q1=Qs[e*65+qi0+1],q2=Qs[e*65+qi0+2],q3=Qs[e*65+qi0+3];
            float k0=Ks[e*65+ki0],k1=Ks[e*65+ki0+1],k2=Ks[e*65+ki0+2],k3=Ks[e*65+ki0+3];
            acc[0][0]+=q0*k0; acc[0][1]+=q0*k1; acc[0][2]+=q0*k2; acc[0][3]+=q0*k3;
            acc[1][0]+=q1*k0; acc[1][1]+=q1*k1; acc[1][2]+=q1*k2; acc[1][3]+=q1*k3;
            acc[2][0]+=q2*k0; acc[2][1]+=q2*k1; acc[2][2]+=q2*k2; acc[2][3]+=q2*k3;
            acc[3][0]+=q3*k0; acc[3][1]+=q3*k1; acc[3][2]+=q3*k2; acc[3][3]+=q3*k3;
        }
    }
    float* Sp = g_Sp + (sl*64+bh)*4096;
    #pragma unroll
    for (int i = 0; i < 4; i++)
        #pragma unroll
        for (int j = 0; j < 4; j++)
            Sp[(qi0+i)*64 + ki0+j] = acc[i][j];
}

__global__ void softmax_kernel(){
    const int bh = blockIdx.x, tid = threadIdx.x;
    const int w = tid>>5, lane = tid&31;
    const float scale = 0.011048543456039806f;
    for (int q = w*8; q < w*8+8; q++){
        float s0 = 0.f, s1 = 0.f;
        for (int sl = 0; sl < 16; sl++){
            const float* p = g_Sp + (sl*64+bh)*4096 + q*64;
            s0 += p[lane]; s1 += p[lane+32];
        }
        s0 *= scale; s1 *= scale;
        float mx = fmaxf(s0, s1);
        for (int o = 16; o; o >>= 1) mx = fmaxf(mx, __shfl_xor_sync(~0u, mx, o));
        float e0 = __expf(s0-mx), e1 = __expf(s1-mx);
        float sum = e0+e1;
        for (int o = 16; o; o >>= 1) sum += __shfl_xor_sync(~0u, sum, o);
        float inv = 1.f/sum;
        g_P[bh*4096 + q*64 + lane]    = e0*inv;
        g_P[bh*4096 + q*64 + lane+32] = e1*inv;
    }
}

// ---------- PV ----------
__global__ __launch_bounds__(256) void attn_pv_kernel(){
    __shared__ float Ps[4096];
    __shared__ float Vs[16*256];
    const int bh = blockIdx.x>>5, ec = blockIdx.x&31, e0 = ec*256;
    const int tid = threadIdx.x;
    for (int i = tid; i < 4096; i += 256) Ps[i] = g_P[bh*4096 + i];
    const int q0 = (tid>>5)*8, es = tid&31;
    const float* Vg = g_v + bh*(64*EE);
    float acc[8][8] = {};
    for (int kc = 0; kc < 4; kc++){
        __syncthreads();
        for (int i = tid; i < 4096; i += 256){
            int k = i>>8, e = i&255;
            Vs[i] = Vg[(kc*16+k)*EE + e0 + e];
        }
        __syncthreads();
        #pragma unroll
        for (int k = 0; k < 16; k++){
            float4 v0 = *(const float4*)&Vs[k*256 + es*8];
            float4 v1 = *(const float4*)&Vs[k*256 + es*8 + 4];
            #pragma unroll
            for (int i = 0; i < 8; i++){
                float p = Ps[(q0+i)*64 + kc*16 + k];
                acc[i][0]+=p*v0.x; acc[i][1]+=p*v0.y; acc[i][2]+=p*v0.z; acc[i][3]+=p*v0.w;
                acc[i][4]+=p*v1.x; acc[i][5]+=p*v1.y; acc[i][6]+=p*v1.z; acc[i][7]+=p*v1.w;
            }
        }
    }
    const int b = bh>>3, h = bh&7;
    const int eg = e0 + es*8;
    const int d = eg>>10, py = (eg>>5)&31, px = eg&31;
    #pragma unroll
    for (int i = 0; i < 8; i++){
        int q = q0+i, oy = q>>3, ox = q&7;
        float* dst = g_y + (b*CC + h*8 + d)*HWSZ + (oy*32+py)*256 + ox*32 + px;
        *(float4*)dst     = make_float4(acc[i][0],acc[i][1],acc[i][2],acc[i][3]);
        *(float4*)(dst+4) = make_float4(acc[i][4],acc[i][5],acc[i][6],acc[i][7]);
    }
}

// ---------- tf32 mma.sync conv: tile 8x16 pixels, D[128,64] = A[128,576] W^T ----------
template<int D>
__global__ __launch_bounds__(128) void conv_mma_kernel(
        const float* __restrict__ src, const float* __restrict__ gw,
        const float* __restrict__ bias, const float* __restrict__ resid,
        float* __restrict__ dst){
    constexpr int ROWS = 8 + 2*D, COLS = 16 + 2*D, RC = ROWS*COLS;
    constexpr int SA = (D == 1) ? 184 : 248;    // ci stride (pad: stride%32 == 24)
    extern __shared__ float sm[];
    float* raw = sm;            // [64][SA]
    float* bs  = sm + 64*SA;    // [64][72]
    const int tid = threadIdx.x, w = tid>>5, gid = (tid&31)>>2, tig = tid&3;
    const int b = blockIdx.z, y0 = blockIdx.y*8, x0 = blockIdx.x*16;

    for (int i = tid; i < 64*RC; i += 128){
        int ci = i/RC, rem = i - ci*RC;
        int r = rem/COLS, c2 = rem - r*COLS;
        int yg = refl(y0 - D + r, HH), xg = refl(x0 - D + c2, WW);
        raw[ci*SA + rem] = __uint_as_float(f2tf32(src[(b*64+ci)*HWSZ + yg*256 + xg]));
    }

    float acc[2][8][4] = {};
    for (int tap = 0; tap < 9; tap++){
        __syncthreads();
        for (int f = tid; f < 1024; f += 128){
            int ci = f>>4, o4 = (f&15)<<2;
            *(float4*)&bs[ci*72 + o4] = *(const float4*)&gw[tap*4096 + ci*64 + o4];
        }
        __syncthreads();
        const int dy = tap/3, dx = tap - dy*3;
        const int rowA = w*2 + dy*D;
        const int colA = gid + dx*D;
        for (int kc = 0; kc < 8; kc++){
            const int k0 = kc*8;
            uint32_t bf0[8], bf1[8];
            #pragma unroll
            for (int nt = 0; nt < 8; nt++){
                bf0[nt] = __float_as_uint(bs[(k0+tig)*72 + nt*8 + gid]);
                bf1[nt] = __float_as_uint(bs[(k0+tig+4)*72 + nt*8 + gid]);
            }
            #pragma unroll
            for (int mt = 0; mt < 2; mt++){
                const float* ra = raw + (k0+tig)*SA + (rowA+mt)*COLS + colA;
                const float* rb = raw + (k0+tig+4)*SA + (rowA+mt)*COLS + colA;
                uint32_t a0 = __float_as_uint(ra[0]), a1 = __float_as_uint(ra[8]);
                uint32_t a2 = __float_as_uint(rb[0]), a3 = __float_as_uint(rb[8]);
                #pragma unroll
                for (int nt = 0; nt < 8; nt++)
                    mma8(acc[mt][nt], a0, a1, a2, a3, bf0[nt], bf1[nt]);
            }
        }
    }

    float bv0[8], bv1[8];
    #pragma unroll
    for (int nt = 0; nt < 8; nt++){
        bv0[nt] = __ldg(&bias[nt*8 + tig*2]);
        bv1[nt] = __ldg(&bias[nt*8 + tig*2 + 1]);
    }
    #pragma unroll
    for (int mt = 0; mt < 2; mt++){
        const int yy = y0 + w*2 + mt;
        const int rowbase = b*64*HWSZ + yy*256 + x0 + gid;
        #pragma unroll
        for (int nt = 0; nt < 8; nt++){
            const int a00 = rowbase + (nt*8 + tig*2)*HWSZ;
            float v0 = lrelu(acc[mt][nt][0] + bv0[nt]);
            float v1 = lrelu(acc[mt][nt][1] + bv1[nt]);
            float v2 = lrelu(acc[mt][nt][2] + bv0[nt]);
            float v3 = lrelu(acc[mt][nt][3] + bv1[nt]);
            if (resid){
                v0 += resid[a00];
                v1 += resid[a00 + HWSZ];
                v2 += resid[a00 + 8];
                v3 += resid[a00 + HWSZ + 8];
            }
            dst[a00]            = v0;
            dst[a00 + HWSZ]     = v1;
            dst[a00 + 8]        = v2;
            dst[a00 + HWSZ + 8] = v3;
        }
    }
}

extern "C" void kernel_launch(void* const* d_in, const int* in_sizes, int n_in,
                              void* d_out, int out_size){
    const float* x   = (const float*)d_in[0];
    const float* wq  = (const float*)d_in[2];
    const float* bq  = (const float*)d_in[3];
    const float* wk  = (const float*)d_in[4];
    const float* bk  = (const float*)d_in[5];
    const float* wv  = (const float*)d_in[6];
    const float* bv  = (const float*)d_in[7];
    const float* wo  = (const float*)d_in[8];
    const float* bo  = (const float*)d_in[9];
    const float* wf1 = (const float*)d_in[10];
    const float* bf1 = (const float*)d_in[11];
    const float* wf2 = (const float*)d_in[12];
    const float* bf2 = (const float*)d_in[13];
    float* out = (float*)d_out;

    float *py, *px1, *pt, *pwt;
    cudaGetSymbolAddress((void**)&py,  g_y);
    cudaGetSymbolAddress((void**)&px1, g_x1);
    cudaGetSymbolAddress((void**)&pt,  g_t);
    cudaGetSymbolAddress((void**)&pwt, g_wt);

    const int QKV_SMEM = (12288 + 192 + 4096) * 4;
    const int SM1 = (64*184 + 64*72) * 4;   // 65536
    const int SM2 = (64*248 + 64*72) * 4;   // 81920
    cudaFuncSetAttribute(qkv_kernel, cudaFuncAttributeMaxDynamicSharedMemorySize, QKV_SMEM);
    cudaFuncSetAttribute(conv_mma_kernel<1>, cudaFuncAttributeMaxDynamicSharedMemorySize, SM1);
    cudaFuncSetAttribute(conv_mma_kernel<2>, cudaFuncAttributeMaxDynamicSharedMemorySize, SM2);

    xform_kernel<<<144, 256>>>(wq, bq, wk, bk, wv, bv, wo, wf1, wf2);
    qkv_kernel<<<dim3(WW/64, HH, BB), 256, QKV_SMEM>>>(x);
    attn_scores_kernel<<<1024, 256>>>();
    softmax_kernel<<<64, 256>>>();
    attn_pv_kernel<<<2048, 256>>>();
    dim3 cg(WW/16, HH/8, BB);
    conv_mma_kernel<1><<<cg, 128, SM1>>>(py,  pwt,           bo,  x,       px1);
    conv_mma_kernel<2><<<cg, 128, SM2>>>(px1, pwt + 36864,   bf1, nullptr, pt);
    conv_mma_kernel<1><<<cg, 128, SM1>>>(pt,  pwt + 2*36864, bf2, px1,     out);
}